// round 9
// baseline (speedup 1.0000x reference)
#include <cuda_runtime.h>
#include <cuda_bf16.h>
#include <cstdint>

#define NP 50000
#define NPPAD 50176           // 196 * 256
#define NTOP 256
#define BATCH 1024
#define HALF_X 6400000
#define HALF_I 131072
#define KLB 25000
#define NTILES 196            // n-tiles of 256
#define NG 18

// dynamic smem layout (byte offsets); [kg][row] 16B-unit layouts, no swizzle
#define SMA_H 0               // A hi: 32 kg x 128 rows x 16B = 64KB
#define SMA_L 65536           // A lo: 64KB
#define SMB   131072          // B: 2 stages x (hi 16KB + lo 16KB) = 64KB
#define SMO_RED 196608        // 128 x 4 float = 2KB
#define SMT_TOT 198656

__device__ __align__(256) __nv_bfloat16 g_Bh[NPPAD * NTOP];
__device__ __align__(256) __nv_bfloat16 g_Bl[NPPAD * NTOP];
__device__ __align__(256) __nv_bfloat16 g_Ah[BATCH * NTOP];
__device__ __align__(256) __nv_bfloat16 g_Al[BATCH * NTOP];
__device__ float2 g_svrv[NPPAD];
__device__ float g_su[BATCH], g_ru[BATCH];
__device__ float g_partial[BATCH * NTILES];
__device__ float g_kldb[BATCH], g_rp[KLB];

// ---------- PTX helpers (plain sm_100-legal) ----------
__device__ __forceinline__ uint32_t smem_u32(const void* p) {
  uint32_t a;
  asm("{ .reg .u64 t; cvta.to.shared.u64 t, %1; cvt.u32.u64 %0, t; }" : "=r"(a) : "l"(p));
  return a;
}
__device__ __forceinline__ void cpa16(uint32_t d, const void* s) {
  asm volatile("cp.async.cg.shared.global [%0], [%1], 16;" :: "r"(d), "l"(s));
}
#define CPCOMMIT() asm volatile("cp.async.commit_group;" ::: "memory")
#define CPWAIT0()  asm volatile("cp.async.wait_group 0;" ::: "memory")

#define LDSM4(r, addr) \
  asm volatile("ldmatrix.sync.aligned.m8n8.x4.shared.b16 {%0,%1,%2,%3}, [%4];" \
    : "=r"((r)[0]), "=r"((r)[1]), "=r"((r)[2]), "=r"((r)[3]) : "r"(addr))

#define MMA16816(d, a, b0r, b1r) \
  asm volatile("mma.sync.aligned.m16n8k16.row.col.f32.bf16.bf16.f32 " \
    "{%0,%1,%2,%3}, {%4,%5,%6,%7}, {%8,%9}, {%0,%1,%2,%3};" \
    : "+f"((d)[0]), "+f"((d)[1]), "+f"((d)[2]), "+f"((d)[3]) \
    : "r"((a)[0]), "r"((a)[1]), "r"((a)[2]), "r"((a)[3]), "r"(b0r), "r"(b1r))

// ---------- Threefry-2x32 (exact JAX) ----------
__host__ __device__ __forceinline__ void tf2x32(unsigned k0, unsigned k1,
                                                unsigned c0, unsigned c1,
                                                unsigned& o0, unsigned& o1) {
  unsigned ks2 = k0 ^ k1 ^ 0x1BD11BDAu;
  unsigned x0 = c0 + k0, x1 = c1 + k1;
#define TF_R(d) { x0 += x1; x1 = (x1 << (d)) | (x1 >> (32 - (d))); x1 ^= x0; }
  TF_R(13) TF_R(15) TF_R(26) TF_R(6)   x0 += k1;  x1 += ks2 + 1u;
  TF_R(17) TF_R(29) TF_R(16) TF_R(24)  x0 += ks2; x1 += k0 + 2u;
  TF_R(13) TF_R(15) TF_R(26) TF_R(6)   x0 += k0;  x1 += k1 + 3u;
  TF_R(17) TF_R(29) TF_R(16) TF_R(24)  x0 += k1;  x1 += ks2 + 4u;
  TF_R(13) TF_R(15) TF_R(26) TF_R(6)   x0 += ks2; x1 += k0 + 5u;
#undef TF_R
  o0 = x0; o1 = x1;
}
__device__ __forceinline__ float bits_to_normal(unsigned bits) {
  float f = __uint_as_float((bits >> 9) | 0x3f800000u) - 1.0f;
  float lo = __uint_as_float(0xBF7FFFFFu);
  return 1.41421356237f * erfinvf(fmaxf(lo, fmaf(f, 2.0f, lo)));
}
__device__ __forceinline__ float wred(float v) {
#pragma unroll
  for (int o = 16; o > 0; o >>= 1) v += __shfl_xor_sync(0xffffffffu, v, o);
  return v;
}

// ---------- warp-per-row fused sample + double transform ----------
__device__ __forceinline__ void row_transform(const float* x, float sx, int row,
                                              __nv_bfloat16* Bh, __nv_bfloat16* Bl,
                                              float2* svrv, float* su, float* ru,
                                              int lane, int is_batch) {
  float s1 = 1.f + sqrtf(1.f + sx);
  float sy = sx / (s1 * s1);
  float s2 = 1.f + sqrtf(1.f + sy);
  float scale = 1.f / (s1 * s2);
#pragma unroll
  for (int k = 0; k < 8; k++) {
    float p = x[k] * scale;
    __nv_bfloat16 hi = __float2bfloat16_rn(p);
    int col = k * 32 + lane;
    Bh[row * NTOP + col] = hi;
    Bl[row * NTOP + col] = __float2bfloat16_rn(p - __bfloat162float(hi));
  }
  if (lane == 0) {
    float sp = sy / (s2 * s2);
    float sv = fminf(fmaxf(sp, 0.f), 1.f - 1e-5f);
    float rv = 1.f / (1.f - sv);
    if (is_batch) { su[row] = sv; ru[row] = rv; }
    else svrv[row] = make_float2(sv, rv);
  }
}

__global__ __launch_bounds__(256) void kA(const float* __restrict__ mu,
                                          const float* __restrict__ lv,
                                          unsigned kx0, unsigned kx1) {
  int w = threadIdx.x >> 5, lane = threadIdx.x & 31;
  int r = blockIdx.x * 8 + w;
  int r2 = r + 25000;
  float x1[8], x2[8];
  float sx1 = 0.f, sx2 = 0.f, kl = 0.f;
#pragma unroll
  for (int k = 0; k < 8; k++) {
    int g = r * NTOP + k * 32 + lane;
    unsigned b0, b1;
    tf2x32(kx0, kx1, (unsigned)g, (unsigned)(g + HALF_X), b0, b1);
    float m1 = mu[g], l1 = lv[g];
    float sd1 = expf(0.5f * l1);
    x1[k] = fmaf(bits_to_normal(b0), sd1, m1);
    kl += 1.0f + l1 - m1 * m1 - sd1 * sd1;
    int g2 = g + HALF_X;
    float m2 = mu[g2], l2 = lv[g2];
    float sd2 = expf(0.5f * l2);
    x2[k] = fmaf(bits_to_normal(b1), sd2, m2);
    kl += 1.0f + l2 - m2 * m2 - sd2 * sd2;
    sx1 += x1[k] * x1[k];
    sx2 += x2[k] * x2[k];
  }
  sx1 = wred(sx1); sx2 = wred(sx2); kl = wred(kl);
  row_transform(x1, sx1, r,  g_Bh, g_Bl, g_svrv, 0, 0, lane, 0);
  row_transform(x2, sx2, r2, g_Bh, g_Bl, g_svrv, 0, 0, lane, 0);
  if (lane == 0) g_rp[r] = kl;
}

__global__ __launch_bounds__(256) void kB(const float* __restrict__ mu,
                                          const float* __restrict__ lv,
                                          const int* __restrict__ iidx,
                                          unsigned ki0, unsigned ki1) {
  int w = threadIdx.x >> 5, lane = threadIdx.x & 31;
  int r = blockIdx.x * 8 + w;
  int r2 = r + 512;
  int i1 = iidx[r], i2 = iidx[r2];
  float x1[8], x2[8];
  float sx1 = 0.f, sx2 = 0.f;
#pragma unroll
  for (int k = 0; k < 8; k++) {
    int col = k * 32 + lane;
    int f = r * NTOP + col;
    unsigned b0, b1;
    tf2x32(ki0, ki1, (unsigned)f, (unsigned)(f + HALF_I), b0, b1);
    int a0 = i1 * NTOP + col, a1 = i2 * NTOP + col;
    x1[k] = fmaf(bits_to_normal(b0), expf(0.5f * lv[a0]), mu[a0]);
    x2[k] = fmaf(bits_to_normal(b1), expf(0.5f * lv[a1]), mu[a1]);
    sx1 += x1[k] * x1[k];
    sx2 += x2[k] * x2[k];
  }
  sx1 = wred(sx1); sx2 = wred(sx2);
  row_transform(x1, sx1, r,  g_Ah, g_Al, 0, g_su, g_ru, lane, 1);
  row_transform(x2, sx2, r2, g_Ah, g_Al, 0, g_su, g_ru, lane, 1);
}

// ---------- K5: persistent mma.sync bf16x3 GEMM, CTA 128x256, 16 warps 32x64 ----------
__global__ __launch_bounds__(512, 1) void k5_gemm() {
  extern __shared__ char smc[];
  uint32_t sb = smem_u32(smc);
  int t = threadIdx.x, w = t >> 5, lane = t & 31;
  int wm = w & 3, wn = w >> 2;          // 4 m-blocks of 32, 4 n-blocks of 64
  int grp = blockIdx.x, b0 = blockIdx.y * 128;
  int ntiles = (NTILES - grp + NG - 1) / NG;
  const char* ahp = (const char*)g_Ah;
  const char* alp = (const char*)g_Al;
  const char* bhp = (const char*)g_Bh;
  const char* blp = (const char*)g_Bl;

  float sub[4], rub2[4];
#pragma unroll
  for (int i = 0; i < 4; i++) {
    int row = b0 + wm * 32 + (i >> 1) * 16 + (lane >> 2) + (i & 1) * 8;
    sub[i] = g_su[row];
    rub2[i] = 2.f * g_ru[row];
  }

  // startup: all of A (hi+lo) in [kg][row]; B tile(grp) chunk0
#pragma unroll
  for (int q = 0; q < 8; q++) {
    int idx = q * 512 + t, kg = idx >> 7, r = idx & 127;
    size_t so = (size_t)(b0 + r) * 512 + kg * 16;
    cpa16(sb + SMA_H + kg * 2048 + r * 16, ahp + so);
    cpa16(sb + SMA_L + kg * 2048 + r * 16, alp + so);
  }
#pragma unroll
  for (int q = 0; q < 2; q++) {
    int idx = q * 512 + t, kgl = idx >> 8, r = idx & 255;
    size_t so = (size_t)(grp * 256 + r) * 512 + kgl * 16;
    cpa16(sb + SMB + kgl * 4096 + r * 16,         bhp + so);
    cpa16(sb + SMB + kgl * 4096 + r * 16 + 16384, blp + so);
  }
  CPCOMMIT();

  uint32_t arow0 = (uint32_t)((wm * 32 + (lane & 15)) * 16);   // +mt*256
  uint32_t brow0 = (uint32_t)((wn * 64 + (lane & 15)) * 16);   // +q*256
  uint32_t ly = (uint32_t)(lane >> 4);

  for (int ti = 0; ti < ntiles; ti++) {
    int nt = grp + ti * NG;
    float acc[2][8][4];
#pragma unroll
    for (int a = 0; a < 2; a++)
#pragma unroll
      for (int b = 0; b < 8; b++)
#pragma unroll
        for (int e = 0; e < 4; e++) acc[a][b][e] = 0.f;

    for (int c = 0; c < 8; c++) {      // k32 chunks, stage = c&1
      CPWAIT0();
      __syncthreads();
      bool has_next = (c < 7) || (ti < ntiles - 1);
      if (has_next) {
        int c2 = (c < 7) ? c + 1 : 0;
        int nrowb = (c < 7) ? nt * 256 : (nt + NG) * 256;
        uint32_t bs = sb + SMB + ((c + 1) & 1) * 32768;
#pragma unroll
        for (int q = 0; q < 2; q++) {
          int idx = q * 512 + t, kgl = idx >> 8, r = idx & 255;
          size_t so = (size_t)(nrowb + r) * 512 + c2 * 64 + kgl * 16;
          cpa16(bs + kgl * 4096 + r * 16,         bhp + so);
          cpa16(bs + kgl * 4096 + r * 16 + 16384, blp + so);
        }
        CPCOMMIT();
      }

      uint32_t bbase = sb + SMB + (c & 1) * 32768;
#pragma unroll
      for (int s = 0; s < 2; s++) {
        uint32_t aaddr = sb + SMA_H + (c * 4 + s * 2 + ly) * 2048 + arow0;
        uint32_t baddr = bbase + (s * 2 + ly) * 4096 + brow0;
        uint32_t aH[2][4], aL[2][4];
#pragma unroll
        for (int mt = 0; mt < 2; mt++) {
          LDSM4(aH[mt], aaddr + mt * 256);
          LDSM4(aL[mt], aaddr + mt * 256 + 65536);
        }
#pragma unroll
        for (int qp = 0; qp < 2; qp++) {
          uint32_t bH[2][4], bL[2][4];
#pragma unroll
          for (int qq = 0; qq < 2; qq++) {
            uint32_t bd = baddr + (qp * 2 + qq) * 256;
            LDSM4(bH[qq], bd);
            LDSM4(bL[qq], bd + 16384);
          }
#pragma unroll
          for (int qq = 0; qq < 2; qq++)
#pragma unroll
            for (int mt = 0; mt < 2; mt++) {
              MMA16816(acc[mt][(qp * 2 + qq) * 2],     aH[mt], bH[qq][0], bH[qq][2]);
              MMA16816(acc[mt][(qp * 2 + qq) * 2 + 1], aH[mt], bH[qq][1], bH[qq][3]);
            }
#pragma unroll
          for (int qq = 0; qq < 2; qq++)
#pragma unroll
            for (int mt = 0; mt < 2; mt++) {
              MMA16816(acc[mt][(qp * 2 + qq) * 2],     aL[mt], bH[qq][0], bH[qq][2]);
              MMA16816(acc[mt][(qp * 2 + qq) * 2 + 1], aL[mt], bH[qq][1], bH[qq][3]);
            }
#pragma unroll
          for (int qq = 0; qq < 2; qq++)
#pragma unroll
            for (int mt = 0; mt < 2; mt++) {
              MMA16816(acc[mt][(qp * 2 + qq) * 2],     aH[mt], bL[qq][0], bL[qq][2]);
              MMA16816(acc[mt][(qp * 2 + qq) * 2 + 1], aH[mt], bL[qq][1], bL[qq][3]);
            }
        }
      }
    }

    // epilogue: e = x + sqrt(x^2-1); svrv direct from L2
    int nbase = nt * 256;
    int limit = NP - nbase;
    float rs[4] = {0.f, 0.f, 0.f, 0.f};
#pragma unroll
    for (int j = 0; j < 8; j++)
#pragma unroll
      for (int e2 = 0; e2 < 2; e2++) {
        int nl = wn * 64 + j * 8 + 2 * (lane & 3) + e2;
        if (nl < limit) {
          float2 sr = __ldg(&g_svrv[nbase + nl]);
#pragma unroll
          for (int mt = 0; mt < 2; mt++)
#pragma unroll
            for (int eh = 0; eh < 2; eh++) {
              int ri = mt * 2 + eh;
              float qd = fmaxf(fmaf(acc[mt][j][eh * 2 + e2], -2.f, sub[ri] + sr.x), 0.f);
              float xx = fmaxf(fmaf(qd, rub2[ri] * sr.y, 1.f), 1.0f + 1e-7f);
              float s;
              asm("sqrt.approx.f32 %0, %1;" : "=f"(s) : "f"(fmaf(xx, xx, -1.f)));
              rs[ri] += xx + s;
            }
        }
      }
    float* red = (float*)(smc + SMO_RED);
#pragma unroll
    for (int i = 0; i < 4; i++) {
      rs[i] += __shfl_xor_sync(0xffffffffu, rs[i], 1);
      rs[i] += __shfl_xor_sync(0xffffffffu, rs[i], 2);
      if ((lane & 3) == 0) {
        int row = wm * 32 + (i >> 1) * 16 + (lane >> 2) + (i & 1) * 8;
        red[row * 4 + wn] = rs[i];
      }
    }
    __syncthreads();
    if (t < 128)
      g_partial[(b0 + t) * NTILES + nt] =
          (red[t * 4] + red[t * 4 + 1]) + (red[t * 4 + 2] + red[t * 4 + 3]);
    __syncthreads();
  }
}

// ---------- tails (k7 fused into k6) ----------
__global__ __launch_bounds__(256) void k6_lse(const float* __restrict__ pij,
                                              const int* __restrict__ jidx) {
  int b = blockIdx.x, t = threadIdx.x;
  int jb = jidx[b];
  float av = __bfloat162float(g_Ah[b * NTOP + t]) + __bfloat162float(g_Al[b * NTOP + t]);
  float vv = __bfloat162float(g_Bh[jb * NTOP + t]) + __bfloat162float(g_Bl[jb * NTOP + t]);
  float pr = av * vv;
  float s = 0.f;
  for (int q = t; q < NTILES; q += 256) s += g_partial[b * NTILES + q];
  __shared__ float sh[256], sh2[256];
  sh[t] = s; sh2[t] = pr; __syncthreads();
  for (int w = 128; w > 0; w >>= 1) {
    if (t < w) { sh[t] += sh[t + w]; sh2[t] += sh2[t + w]; }
    __syncthreads();
  }
  if (t == 0) {
    float2 sr = g_svrv[jb];
    float sq = fmaxf(g_su[b] + sr.x - 2.f * sh2[0], 0.f);
    float xx = fmaxf(fmaf(2.f * sq, g_ru[b] * sr.y, 1.f), 1.0f + 1e-7f);
    float dj = logf(xx + sqrtf(fmaf(xx, xx, -1.f)));
    float pb = pij[b];
    g_kldb[b] = pb * (logf(pb) - (dj - logf(sh[0])));
  }
}

__global__ __launch_bounds__(256) void k8_final(float* __restrict__ out) {
  int t = threadIdx.x;
  __shared__ double shd[256];
  double s1 = 0.0, s2 = 0.0;
  for (int b = t; b < BATCH; b += 256) s1 += (double)g_kldb[b];
  for (int q = t; q < KLB; q += 256) s2 += (double)g_rp[q];
  shd[t] = s1; __syncthreads();
  for (int w = 128; w > 0; w >>= 1) { if (t < w) shd[t] += shd[t + w]; __syncthreads(); }
  double kldsum = shd[0]; __syncthreads();
  shd[t] = s2; __syncthreads();
  for (int w = 128; w > 0; w >>= 1) { if (t < w) shd[t] += shd[t + w]; __syncthreads(); }
  if (t == 0)
    out[0] = (float)(kldsum + (-0.5 * shd[0]) * (1024.0 / (50000.0 * 50000.0)));
}

extern "C" void kernel_launch(void* const* d_in, const int* in_sizes, int n_in,
                              void* d_out, int out_size) {
  const float* pij = (const float*)d_in[0];
  const float* mu  = (const float*)d_in[1];
  const float* lv  = (const float*)d_in[2];
  const int*   ii  = (const int*)d_in[3];
  const int*   jj  = (const int*)d_in[4];
  float* out = (float*)d_out;

  unsigned A0, B0, A1, B1;
  tf2x32(0u, 42u, 0u, 2u, A0, B0);   // kx
  tf2x32(0u, 42u, 1u, 3u, A1, B1);   // ki

  cudaFuncSetAttribute(k5_gemm, cudaFuncAttributeMaxDynamicSharedMemorySize, SMT_TOT);

  kA<<<3125, 256>>>(mu, lv, A0, A1);
  kB<<<64, 256>>>(mu, lv, ii, B0, B1);
  k5_gemm<<<dim3(NG, 8), 512, SMT_TOT>>>();
  k6_lse<<<BATCH, 256>>>(pij, jj);
  k8_final<<<1, 256>>>(out);
}